// round 6
// baseline (speedup 1.0000x reference)
#include <cuda_runtime.h>

#define BATCH 4
#define NPTS 8192
#define PAD 32
#define STRIDE (NPTS + 2 * PAD)
#define BINS 8192
#define SORT_THREADS 1024
#define W 1536
#define HALF 256                             // phase-A half-width
#define NN_THREADS 128
#define QPB 128
#define NN_BLOCKS_X (NPTS / QPB)             // 64
#define NN_BLOCKS (NN_BLOCKS_X * 8)          // 512
#define FULLMASK 0xffffffffu
#define DELTA 0.005f   // > x-bucket width (12/8192); certificate margin

__device__ float4 g_pts[8][STRIDE];
__device__ float g_bsum[NN_BLOCKS];
__device__ unsigned g_count;   // zero-init; reset by last block each run

__device__ __forceinline__ int bucket(float x) {
    int b = (int)((x + 6.0f) * (BINS / 12.0f));
    return min(max(b, 0), BINS - 1);
}
__device__ __forceinline__ float dquad(float m2x, float m2y, float m2z, float4 t) {
    return fmaf(m2x, t.x, fmaf(m2y, t.y, fmaf(m2z, t.z, t.w)));
}

// ---------------------------------------------------------------------------
// Counting sort by 13-bit quantized x. One block per (set,batch).
// ---------------------------------------------------------------------------
__global__ __launch_bounds__(SORT_THREADS)
void sort_kernel(const float* __restrict__ p1, const float* __restrict__ p2) {
    __shared__ unsigned hist[BINS];
    __shared__ unsigned wtot[32];
    const int tid = threadIdx.x, lane = tid & 31, wid = tid >> 5;
    const int set = blockIdx.x >> 2;
    const int b = blockIdx.x & 3;
    const float* __restrict__ P = (set ? p2 : p1) + (size_t)b * NPTS * 3;

    for (int i = tid; i < BINS; i += SORT_THREADS) hist[i] = 0;
    __syncthreads();

    float xv[8], yv[8], zv[8];
#pragma unroll
    for (int k = 0; k < 8; k++) {
        int i = tid + k * SORT_THREADS;
        xv[k] = P[3 * i]; yv[k] = P[3 * i + 1]; zv[k] = P[3 * i + 2];
        atomicAdd(&hist[bucket(xv[k])], 1u);
    }
    __syncthreads();

    const int base = tid * 8;
    unsigned loc[8], s = 0;
#pragma unroll
    for (int j = 0; j < 8; j++) { loc[j] = s; s += hist[base + j]; }
    unsigned v = s;
#pragma unroll
    for (int o = 1; o < 32; o <<= 1) {
        unsigned n = __shfl_up_sync(FULLMASK, v, o);
        if (lane >= o) v += n;
    }
    if (lane == 31) wtot[wid] = v;
    __syncthreads();
    if (tid < 32) {
        unsigned w = wtot[tid];
#pragma unroll
        for (int o = 1; o < 32; o <<= 1) {
            unsigned n = __shfl_up_sync(FULLMASK, w, o);
            if (tid >= o) w += n;
        }
        wtot[tid] = w;
    }
    __syncthreads();
    unsigned thr_excl = v - s + (wid ? wtot[wid - 1] : 0u);
    __syncthreads();
#pragma unroll
    for (int j = 0; j < 8; j++) hist[base + j] = thr_excl + loc[j];
    __syncthreads();

    float4* dst = g_pts[blockIdx.x];
#pragma unroll
    for (int k = 0; k < 8; k++) {
        unsigned pos = atomicAdd(&hist[bucket(xv[k])], 1u);
        dst[PAD + pos] = make_float4(xv[k], yv[k], zv[k],
            xv[k] * xv[k] + yv[k] * yv[k] + zv[k] * zv[k]);
    }
    for (int i = tid; i < PAD; i += SORT_THREADS) {
        dst[i]              = make_float4(-1e30f, 0.f, 0.f, 3.0e38f);
        dst[PAD + NPTS + i] = make_float4( 1e30f, 0.f, 0.f, 3.0e38f);
    }
}

// ---------------------------------------------------------------------------
// NN: speculative fixed 512-target scan (no serialization), then rare
// certificate-driven expansion.
// ---------------------------------------------------------------------------
__global__ __launch_bounds__(NN_THREADS)
void nn_kernel(float* __restrict__ out) {
    __shared__ __align__(16) float4 s_win[W];   // 24 KB
    __shared__ float sred[4];
    __shared__ bool s_last;

    const int tid = threadIdx.x, lane = tid & 31, wid = tid >> 5;
    const int db  = blockIdx.y;
    const int dir = db >> 2, b = db & 3;
    const float4* __restrict__ Q = g_pts[(dir ? 4 : 0) + b];
    const float4* __restrict__ T = g_pts[(dir ? 0 : 4) + b];

    const float4 q = Q[PAD + blockIdx.x * QPB + tid];
    const float qx = q.x, qsq = q.w;
    const float m2x = -2.f * q.x, m2y = -2.f * q.y, m2z = -2.f * q.z;

    // Block window placement.
    const float xmid = Q[PAD + blockIdx.x * QPB + QPB / 2].x;
    int lo = 0, hi = NPTS;
#pragma unroll
    for (int s = 0; s < 13; s++) {
        int mid = (lo + hi) >> 1;
        if (T[PAD + mid].x < xmid) lo = mid + 1; else hi = mid;
    }
    const int wstart = min(max(lo - W / 2, 0), NPTS - W);

    for (int i = tid; i < W; i += NN_THREADS)
        s_win[i] = T[PAD + wstart + i];
    __syncthreads();

    // Per-warp center in window (warp-uniform).
    const float xw = __shfl_sync(FULLMASK, qx, 16);
    int l2 = 0, h2 = W;
#pragma unroll
    for (int s = 0; s < 11; s++) {
        int mid = (l2 + h2) >> 1;
        if (s_win[mid].x < xw) l2 = mid + 1; else h2 = mid;
    }
    const int c = min(max(l2, HALF), W - HALF);

    // ---- Phase A: fixed 2*HALF targets, zero exit checks, 8-way ILP ----
    float acc[8];
#pragma unroll
    for (int k = 0; k < 8; k++) acc[k] = 3.0e38f;
    const float4* wp = s_win + (c - HALF);
#pragma unroll 2
    for (int j = 0; j < 2 * HALF; j += 8) {
#pragma unroll
        for (int k = 0; k < 8; k++)
            acc[k] = fminf(acc[k], dquad(m2x, m2y, m2z, wp[j + k]));
    }
    float bv = fminf(fminf(fminf(acc[0], acc[1]), fminf(acc[2], acc[3])),
                     fminf(fminf(acc[4], acc[5]), fminf(acc[6], acc[7])));

    // ---- Certificate; phase B only for uncertified sides (rare) ----
    int pr = c + HALF, pl = c - HALF;
    float ttr = s_win[pr - 1].x - qx - DELTA;
    float ttl = qx - s_win[pl].x - DELTA;
    bool rdone = __all_sync(FULLMASK, (ttr > 0.f) && (ttr * ttr >= bv + qsq));
    bool ldone = __all_sync(FULLMASK, (ttl > 0.f) && (ttl * ttl >= bv + qsq));
    bool gr = false, gl = false;

    while (!(rdone && ldone)) {
        if (!rdone) {
            if (pr + 32 > W) { gr = true; rdone = true; }
            else {
                float c0 = bv, c1 = 3.0e38f, c2v = 3.0e38f, c3 = 3.0e38f;
#pragma unroll
                for (int j = 0; j < 32; j += 4) {
                    c0  = fminf(c0,  dquad(m2x, m2y, m2z, s_win[pr + j]));
                    c1  = fminf(c1,  dquad(m2x, m2y, m2z, s_win[pr + j + 1]));
                    c2v = fminf(c2v, dquad(m2x, m2y, m2z, s_win[pr + j + 2]));
                    c3  = fminf(c3,  dquad(m2x, m2y, m2z, s_win[pr + j + 3]));
                }
                bv = fminf(fminf(c0, c1), fminf(c2v, c3));
                float tt = s_win[pr + 31].x - qx - DELTA;
                pr += 32;
                rdone = __all_sync(FULLMASK, (tt > 0.f) && (tt * tt >= bv + qsq));
            }
        }
        if (!ldone) {
            if (pl < 32) { gl = true; ldone = true; }
            else {
                pl -= 32;
                float c0 = bv, c1 = 3.0e38f, c2v = 3.0e38f, c3 = 3.0e38f;
#pragma unroll
                for (int j = 0; j < 32; j += 4) {
                    c0  = fminf(c0,  dquad(m2x, m2y, m2z, s_win[pl + j]));
                    c1  = fminf(c1,  dquad(m2x, m2y, m2z, s_win[pl + j + 1]));
                    c2v = fminf(c2v, dquad(m2x, m2y, m2z, s_win[pl + j + 2]));
                    c3  = fminf(c3,  dquad(m2x, m2y, m2z, s_win[pl + j + 3]));
                }
                bv = fminf(fminf(c0, c1), fminf(c2v, c3));
                float tt = qx - s_win[pl].x - DELTA;
                ldone = __all_sync(FULLMASK, (tt > 0.f) && (tt * tt >= bv + qsq));
            }
        }
    }

    // Global continuations past the window (very rare; sentinels terminate).
    int gpr = wstart + pr;
    while (gr) {
        float c0 = bv, c1 = 3.0e38f;
#pragma unroll
        for (int j = 0; j < 32; j += 2) {
            c0 = fminf(c0, dquad(m2x, m2y, m2z, T[PAD + gpr + j]));
            c1 = fminf(c1, dquad(m2x, m2y, m2z, T[PAD + gpr + j + 1]));
        }
        bv = fminf(c0, c1);
        float tt = T[PAD + gpr + 31].x - qx - DELTA;
        gpr += 32;
        gr = !__all_sync(FULLMASK, (tt > 0.f) && (tt * tt >= bv + qsq));
    }
    int gpl = wstart + pl;
    while (gl) {
        gpl -= 32;
        float c0 = bv, c1 = 3.0e38f;
#pragma unroll
        for (int j = 0; j < 32; j += 2) {
            c0 = fminf(c0, dquad(m2x, m2y, m2z, T[PAD + gpl + j]));
            c1 = fminf(c1, dquad(m2x, m2y, m2z, T[PAD + gpl + j + 1]));
        }
        bv = fminf(c0, c1);
        float tt = qx - T[PAD + gpl].x - DELTA;
        gl = !__all_sync(FULLMASK, (tt > 0.f) && (tt * tt >= bv + qsq));
    }

    float d2 = bv + qsq;                    // exact min squared distance

    // Reduction.
#pragma unroll
    for (int o = 16; o; o >>= 1) d2 += __shfl_down_sync(FULLMASK, d2, o);
    if (lane == 0) sred[wid] = d2;
    __syncthreads();
    if (tid == 0) {
        g_bsum[db * NN_BLOCKS_X + blockIdx.x] =
            sred[0] + sred[1] + sred[2] + sred[3];
        __threadfence();
        unsigned t = atomicAdd(&g_count, 1u);
        s_last = (t == NN_BLOCKS - 1);
    }
    __syncthreads();

    if (s_last) {
        __threadfence();
        float w = 0.f;
#pragma unroll
        for (int i = 0; i < NN_BLOCKS / NN_THREADS; i++)      // 4 each
            w += g_bsum[tid + i * NN_THREADS];
#pragma unroll
        for (int o = 16; o; o >>= 1) w += __shfl_down_sync(FULLMASK, w, o);
        if (lane == 0) sred[wid] = w;
        __syncthreads();
        if (tid == 0) {
            out[0] = sred[0] + sred[1] + sred[2] + sred[3];
            g_count = 0u;               // reset for next graph replay
        }
    }
}

extern "C" void kernel_launch(void* const* d_in, const int* in_sizes, int n_in,
                              void* d_out, int out_size) {
    const float* p1 = (const float*)d_in[0];
    const float* p2 = (const float*)d_in[1];
    float* out = (float*)d_out;

    sort_kernel<<<8, SORT_THREADS>>>(p1, p2);
    nn_kernel<<<dim3(NN_BLOCKS_X, 8), NN_THREADS>>>(out);
}